// round 14
// baseline (speedup 1.0000x reference)
#include <cuda_runtime.h>
#include <cuda_fp16.h>
#include <cstdint>

#define EMBD   384
#define FFN_D  1536
#define T_SEQ  200
#define NH     6
#define HS     64
#define BATCH  256
#define M_ROWS (BATCH * T_SEQ)   // 51200
#define LDQ    1152              // fused QKV row stride

// ---------------- scratch (no allocations allowed) ----------------
__device__ __half g_H [M_ROWS * EMBD];     // LN out, fp16 permuted
__device__ __half g_QKV[M_ROWS * LDQ];     // fp16 natural
__device__ __half g_A [M_ROWS * EMBD];     // attn out, fp16 permuted
__device__ float  g_X1[M_ROWS * EMBD];     // fp32 natural
__device__ __half g_F [M_ROWS * FFN_D];    // relu out, fp16 permuted
// fp16 weights: Wt[N][K], k pair-permuted + chunk-swizzled
__device__ __half g_Wqkv[LDQ * EMBD];
__device__ __half g_Wp  [EMBD * EMBD];
__device__ __half g_W1t [FFN_D * EMBD];
__device__ __half g_W2t [EMBD * FFN_D];

// ---------------- permuted fp16 layout ----------------
__device__ __forceinline__ int poff(int m, int k) {
    int b = k & 15;
    int p = b >> 1, o = b & 1;
    int pp = ((p & 3) << 1) | (p >> 2);
    int h = (pp << 1) | o;
    int c = (h >> 2) ^ (m & 3);
    return (k & ~15) | (c << 2) | (h & 3);
}

// ---------------- helpers ----------------
__device__ __forceinline__ uint32_t smem_u32(const void* p) {
    uint32_t a;
    asm("{ .reg .u64 t; cvta.to.shared.u64 t, %1; cvt.u32.u64 %0, t; }"
        : "=r"(a) : "l"(p));
    return a;
}
__device__ __forceinline__ void cp16(uint32_t dst, const void* src) {
    asm volatile("cp.async.cg.shared.global [%0], [%1], 16;" :: "r"(dst), "l"(src));
}
#define CP_COMMIT()  asm volatile("cp.async.commit_group;")
#define CP_WAIT(n)   asm volatile("cp.async.wait_group %0;" :: "n"(n))

// NOTE: non-volatile asm — lets ptxas interleave/schedule mma with LDS.
#define MMA16816(acc, a0, a1, a2, a3, b0, b1)                          \
    asm("mma.sync.aligned.m16n8k16.row.col.f32.f16.f16.f32 "           \
        "{%0,%1,%2,%3}, {%4,%5,%6,%7}, {%8,%9}, {%0,%1,%2,%3};"        \
        : "+f"((acc)[0]), "+f"((acc)[1]), "+f"((acc)[2]), "+f"((acc)[3]) \
        : "r"(a0), "r"(a1), "r"(a2), "r"(a3), "r"(b0), "r"(b1))

// ---------------- weight prep ----------------
__global__ void prep_w(const float* __restrict__ src, __half* __restrict__ dst,
                       int K, int N)
{
    int idx = blockIdx.x * 256 + threadIdx.x;
    if (idx >= K * N) return;
    int k = idx / N, n = idx - k * N;
    dst[(size_t)n * K + poff(n, k)] = __float2half(src[idx]);
}

__global__ void prep_qkv(const float* __restrict__ Wq,
                         const float* __restrict__ Wk,
                         const float* __restrict__ Wv,
                         __half* __restrict__ dst)
{
    int idx = blockIdx.x * 256 + threadIdx.x;
    if (idx >= 3 * EMBD * EMBD) return;
    int which = idx / (EMBD * EMBD);
    int rem = idx - which * EMBD * EMBD;
    int k = rem / EMBD, n = rem - k * EMBD;
    const float* src = (which == 0) ? Wq : (which == 1) ? Wk : Wv;
    dst[(size_t)(which * EMBD + n) * EMBD + poff(n, k)] = __float2half(src[rem]);
}

// ---------------- LayerNorm: warp per row -> fp16 permuted ----------------
__global__ void ln_kernel(const float* __restrict__ x,
                          const float* __restrict__ g,
                          const float* __restrict__ be,
                          __half* __restrict__ out)
{
    int warp = threadIdx.x >> 5, lane = threadIdx.x & 31;
    int row = blockIdx.x * 8 + warp;
    const float4* xr = (const float4*)(x + (size_t)row * EMBD);

    float4 v0 = xr[lane], v1 = xr[lane + 32], v2 = xr[lane + 64];
    float s = v0.x + v0.y + v0.z + v0.w + v1.x + v1.y + v1.z + v1.w
            + v2.x + v2.y + v2.z + v2.w;
    #pragma unroll
    for (int o = 16; o; o >>= 1) s += __shfl_xor_sync(0xffffffffu, s, o);
    float mean = s * (1.0f / EMBD);

    float sq = 0.f;
    #pragma unroll
    for (int c = 0; c < 3; c++) {
        float4 v = c == 0 ? v0 : c == 1 ? v1 : v2;
        float a = v.x - mean, b_ = v.y - mean, cc = v.z - mean, d = v.w - mean;
        sq += a * a + b_ * b_ + cc * cc + d * d;
    }
    #pragma unroll
    for (int o = 16; o; o >>= 1) sq += __shfl_xor_sync(0xffffffffu, sq, o);
    float inv = rsqrtf(sq * (1.0f / EMBD) + 1e-5f);

    __half* orow = out + (size_t)row * EMBD;
    #pragma unroll
    for (int c = 0; c < 3; c++) {
        float4 v = c == 0 ? v0 : c == 1 ? v1 : v2;
        int k0 = c * 128 + lane * 4;
        const float4 gg = *(const float4*)(g + k0);
        const float4 bb = *(const float4*)(be + k0);
        float r0 = (v.x - mean) * inv * gg.x + bb.x;
        float r1 = (v.y - mean) * inv * gg.y + bb.y;
        float r2 = (v.z - mean) * inv * gg.z + bb.z;
        float r3 = (v.w - mean) * inv * gg.w + bb.w;
        *(half2*)(orow + poff(row, k0))     = __floats2half2_rn(r0, r1);
        *(half2*)(orow + poff(row, k0 + 2)) = __floats2half2_rn(r2, r3);
    }
}

// ---------------- fp16 tensor-core GEMM, 4-stage pipeline ----------------
// CTA 128x128, 8 warps (4Mx2N), warp tile 32x64 = 2x8 m16n8k16.
// Dynamic SMEM 64KB: A stages [0,32K), B stages [32K,64K), 8KB per stage.
// EPI: 0 = fp16 natural out, 1 = bias+relu (fp16 permuted), 2 = bias+residual (fp32).
#define GSMEM 65536

template <int EPI>
__global__ void __launch_bounds__(256)
gemm_h(const __half* __restrict__ A,
       const __half* __restrict__ Bt,
       const float* __restrict__ bias,
       const float* __restrict__ add,
       void* __restrict__ Cv,
       int M, int N, int K)
{
    extern __shared__ char gsm[];

    const int tid  = threadIdx.x;
    const int warp = tid >> 5, lane = tid & 31;
    const int wm   = warp >> 1, wn = warp & 1;
    const int gid  = lane >> 2, tig = lane & 3;
    const int m0   = blockIdx.y * 128, n0 = blockIdx.x * 128;

    const int lr = tid >> 1;
    const int lc = (tid & 1) * 32;

    const char* Ag = (const char*)(A + (size_t)(m0 + lr) * K) + lc;
    const char* Bg = (const char*)(Bt + (size_t)(n0 + lr) * K) + lc;
    const uint32_t asm0 = smem_u32(gsm) + lr * 64 + lc;
    const uint32_t bsm0 = asm0 + 32768;

    float acc[2][8][4];
    #pragma unroll
    for (int i = 0; i < 2; i++)
        #pragma unroll
        for (int j = 0; j < 8; j++)
            #pragma unroll
            for (int l = 0; l < 4; l++) acc[i][j][l] = 0.f;

    const int S = K / 32;   // 12 or 48; divisible by 4

    auto load_stage = [&](int buf, int k0) {
        const char* a = Ag + (size_t)k0 * 2;
        const char* b = Bg + (size_t)k0 * 2;
        uint32_t da = asm0 + buf * 8192, db = bsm0 + buf * 8192;
        cp16(da, a); cp16(da + 16, a + 16);
        cp16(db, b); cp16(db + 16, b + 16);
        CP_COMMIT();
    };

    load_stage(0, 0);
    load_stage(1, 32);
    load_stage(2, 64);

    const int cx = ((tig ^ (gid & 3)) << 3);
    const char* asb = (const char*)gsm;
    const char* bsb = asb + 32768;

    auto step = [&](int cur, int nxt, int s) {
        __syncthreads();
        int k3 = (s + 3) * 32;
        if (k3 < K) load_stage(nxt, k3);
        else        CP_COMMIT();
        CP_WAIT(3);

        const char* a_sm = asb + cur * 8192;
        const char* b_sm = bsb + cur * 8192;

        #pragma unroll
        for (int blk = 0; blk < 2; blk++) {
            const int bo = blk * 32 + cx;
            uint2 af[2][2];
            #pragma unroll
            for (int mi = 0; mi < 2; mi++) {
                int base = (wm * 32 + mi * 16 + gid) * 64 + bo;
                af[mi][0] = *(const uint2*)(a_sm + base);
                af[mi][1] = *(const uint2*)(a_sm + base + 8 * 64);
            }
            uint2 bf[8];
            #pragma unroll
            for (int ni = 0; ni < 8; ni++)
                bf[ni] = *(const uint2*)(b_sm + (wn * 64 + ni * 8 + gid) * 64 + bo);

            #pragma unroll
            for (int mi = 0; mi < 2; mi++)
                #pragma unroll
                for (int ni = 0; ni < 8; ni++)
                    MMA16816(acc[mi][ni],
                             af[mi][0].x, af[mi][1].x, af[mi][0].y, af[mi][1].y,
                             bf[ni].x, bf[ni].y);
        }
    };

    #pragma unroll 1
    for (int s = 0; s < S; s += 4) {
        step(0, 3, s);
        step(1, 0, s + 1);
        step(2, 1, s + 2);
        step(3, 2, s + 3);
    }

    // ---------------- epilogue ----------------
    float bx[16];
    if (EPI != 0) {
        #pragma unroll
        for (int ni = 0; ni < 8; ni++) {
            int c = n0 + wn * 64 + ni * 8 + tig * 2;
            bx[ni * 2]     = bias[c];
            bx[ni * 2 + 1] = bias[c + 1];
        }
    }
    #pragma unroll
    for (int mi = 0; mi < 2; mi++) {
        int r = m0 + wm * 32 + mi * 16 + gid;
        #pragma unroll
        for (int ni = 0; ni < 8; ni++) {
            int c = n0 + wn * 64 + ni * 8 + tig * 2;
            float v00 = acc[mi][ni][0], v01 = acc[mi][ni][1];
            float v10 = acc[mi][ni][2], v11 = acc[mi][ni][3];
            if (EPI == 0) {
                __half* Ch = (__half*)Cv;
                *(half2*)(Ch + (size_t)r * N + c)       = __floats2half2_rn(v00, v01);
                *(half2*)(Ch + (size_t)(r + 8) * N + c) = __floats2half2_rn(v10, v11);
            } else if (EPI == 1) {
                v00 = fmaxf(v00 + bx[ni * 2], 0.f);     v01 = fmaxf(v01 + bx[ni * 2 + 1], 0.f);
                v10 = fmaxf(v10 + bx[ni * 2], 0.f);     v11 = fmaxf(v11 + bx[ni * 2 + 1], 0.f);
                __half* Ch = (__half*)Cv;
                int off = poff(r, c);   // (r+8)&3 == r&3
                *(half2*)(Ch + (size_t)r * N + off)       = __floats2half2_rn(v00, v01);
                *(half2*)(Ch + (size_t)(r + 8) * N + off) = __floats2half2_rn(v10, v11);
            } else {
                float* Cf = (float*)Cv;
                float2 r0v = *(const float2*)(add + (size_t)r * N + c);
                float2 r1v = *(const float2*)(add + (size_t)(r + 8) * N + c);
                v00 += bx[ni * 2] + r0v.x; v01 += bx[ni * 2 + 1] + r0v.y;
                v10 += bx[ni * 2] + r1v.x; v11 += bx[ni * 2 + 1] + r1v.y;
                *(float2*)(Cf + (size_t)r * N + c)       = make_float2(v00, v01);
                *(float2*)(Cf + (size_t)(r + 8) * N + c) = make_float2(v10, v11);
            }
        }
    }
}

// ---------------- tensor-core attention, one block per (b,h) ----------------
#define KPAD 208
#define AT_K 4096
#define AT_V 16896
#define AT_P 30208
#define AT_RED 43520
#define ATTN3_SMEM (43520 * 2 + 1024)

__global__ void __launch_bounds__(256)
attn3(const __half* __restrict__ QKV, __half* __restrict__ O)
{
    extern __shared__ __half sm2[];
    __half* Qs = sm2;                  // [64][64]
    __half* Ks = sm2 + AT_K;           // [200][64]
    __half* Vt = sm2 + AT_V;           // [64][208]
    __half* Ps = sm2 + AT_P;           // [64][208]
    float* redm = (float*)(sm2 + AT_RED);   // [2][64]
    float* reds = redm + 128;               // [2][64]

    const int bh = blockIdx.x;
    const int b = bh / NH, h = bh % NH;
    const __half* base = QKV + (size_t)b * T_SEQ * LDQ + h * HS;

    const int tid = threadIdx.x, warp = tid >> 5, lane = tid & 31;
    const int gid = lane >> 2, tig = lane & 3;
    const int rg = warp >> 1, cg = warp & 1;
    const int sw = ((tig ^ (gid & 3)) << 3);
    const half2 zz = __floats2half2_rn(0.f, 0.f);

    for (int i = tid; i < T_SEQ * 32; i += 256) {
        int j = i >> 5, dp = (i & 31) * 2;
        half2 v = *(const half2*)(base + (size_t)j * LDQ + EMBD + dp);
        *(half2*)(Ks + j * 64 + poff(j, dp)) = v;
    }
    for (int i = tid; i < (T_SEQ / 2) * HS; i += 256) {
        int jp = (i >> 6) * 2, d = i & 63;
        __half v0 = base[(size_t)jp * LDQ + 2 * EMBD + d];
        __half v1 = base[(size_t)(jp + 1) * LDQ + 2 * EMBD + d];
        *(half2*)(Vt + d * KPAD + poff(d, jp)) = __halves2half2(v0, v1);
    }
    for (int i = tid; i < HS * 4; i += 256) {
        int d = i >> 2, j = T_SEQ + (i & 3) * 2;
        *(half2*)(Vt + d * KPAD + poff(d, j)) = zz;
    }
    __syncthreads();

    const float scale = 0.05103103630798288f;   // 384^-0.5
    const int m0w = rg * 16;
    const char* qb = (const char*)Qs;
    const char* kbp = (const char*)Ks;
    char* pb = (char*)Ps;
    const char* vb = (const char*)Vt;

    for (int qt = 0; qt < 4; qt++) {
        const int q0 = qt * 64;
        const int jmax = (qt < 3) ? (q0 + 64) : T_SEQ;
        const int NT = (jmax + 7) >> 3;
        const int KB = (jmax + 15) >> 4;

        for (int i = tid; i < 64 * 32; i += 256) {
            int r = i >> 5, dp = (i & 31) * 2;
            int gq = q0 + r;
            half2 v = (gq < T_SEQ) ? *(const half2*)(base + (size_t)gq * LDQ + dp) : zz;
            *(half2*)(Qs + r * 64 + poff(r, dp)) = v;
        }
        __syncthreads();

        float acc[13][4];
        #pragma unroll
        for (int ii = 0; ii < 13; ii++)
            #pragma unroll
            for (int l = 0; l < 4; l++) acc[ii][l] = 0.f;

        #pragma unroll
        for (int kb = 0; kb < 4; kb++) {
            uint2 a0 = *(const uint2*)(qb + (m0w + gid) * 128 + kb * 32 + sw);
            uint2 a1 = *(const uint2*)(qb + (m0w + gid + 8) * 128 + kb * 32 + sw);
            #pragma unroll
            for (int ii = 0; ii < 13; ii++) {
                int jt = cg + ii * 2;
                if (jt < NT) {
                    uint2 bf = *(const uint2*)(kbp + (jt * 8 + gid) * 128 + kb * 32 + sw);
                    MMA16816(acc[ii], a0.x, a1.x, a0.y, a1.y, bf.x, bf.y);
                }
            }
        }

        const int r0 = q0 + m0w + gid, r1 = r0 + 8;
        float mx0 = -1e30f, mx1 = -1e30f;
        #pragma unroll
        for (int ii = 0; ii < 13; ii++) {
            int jt = cg + ii * 2;
            if (jt < NT) {
                int j0 = jt * 8 + tig * 2;
                acc[ii][0] = (j0     <= r0) ? acc[ii][0] * scale : -1e30f;
                acc[ii][1] = (j0 + 1 <= r0) ? acc[ii][1] * scale : -1e30f;
                acc[ii][2] = (j0     <= r1) ? acc[ii][2] * scale : -1e30f;
                acc[ii][3] = (j0 + 1 <= r1) ? acc[ii][3] * scale : -1e30f;
                mx0 = fmaxf(mx0, fmaxf(acc[ii][0], acc[ii][1]));
                mx1 = fmaxf(mx1, fmaxf(acc[ii][2], acc[ii][3]));
            }
        }
        mx0 = fmaxf(mx0, __shfl_xor_sync(0xffffffffu, mx0, 1));
        mx0 = fmaxf(mx0, __shfl_xor_sync(0xffffffffu, mx0, 2));
        mx1 = fmaxf(mx1, __shfl_xor_sync(0xffffffffu, mx1, 1));
        mx1 = fmaxf(mx1, __shfl_xor_sync(0xffffffffu, mx1, 2));
        if (tig == 0) {
            redm[cg * 64 + m0w + gid]     = mx0;
            redm[cg * 64 + m0w + gid + 8] = mx1;
        }
        __syncthreads();
        mx0 = fmaxf(redm[m0w + gid],     redm[64 + m0w + gid]);
        mx1 = fmaxf(redm[m0w + gid + 8], redm[64 + m0w + gid + 8]);

        float s0 = 0.f, s1 = 0.f;
        #pragma unroll
        for (int ii = 0; ii < 13; ii++) {
            int jt = cg + ii * 2;
            if (jt < NT) {
                int j0 = jt * 8 + tig * 2;
                float e00 = __expf(acc[ii][0] - mx0), e01 = __expf(acc[ii][1] - mx0);
                float e10 = __expf(acc[ii][2] - mx1), e11 = __expf(acc[ii][3] - mx1);
                s0 += e00 + e01; s1 += e10 + e11;
                int m_ = m0w + gid;
                *(half2*)(pb + m_ * 416 + poff(m_, j0) * 2) = __floats2half2_rn(e00, e01);
                m_ += 8;
                *(half2*)(pb + m_ * 416 + poff(m_, j0) * 2) = __floats2half2_rn(e10, e11);
            }
        }
        if (qt == 3 && cg) {
            int j0 = T_SEQ + tig * 2;
            int m_ = m0w + gid;
            *(half2*)(pb + m_ * 416 + poff(m_, j0) * 2) = zz;
            m_ += 8;
            *(half2*)(pb + m_ * 416 + poff(m_, j0) * 2) = zz;
        }
        s0 += __shfl_xor_sync(0xffffffffu, s0, 1);
        s0 += __shfl_xor_sync(0xffffffffu, s0, 2);
        s1 += __shfl_xor_sync(0xffffffffu, s1, 1);
        s1 += __shfl_xor_sync(0xffffffffu, s1, 2);
        if (tig == 0) {
            reds[cg * 64 + m0w + gid]     = s0;
            reds[cg * 64 + m0w + gid + 8] = s1;
        }
        __syncthreads();

        float oacc[4][4];
        #pragma unroll
        for (int ni = 0; ni < 4; ni++)
            #pragma unroll
            for (int l = 0; l < 4; l++) oacc[ni][l] = 0.f;

        #pragma unroll
        for (int kb = 0; kb < 13; kb++) {
            if (kb < KB) {
                uint2 a0 = *(const uint2*)(pb + (m0w + gid) * 416 + kb * 32 + sw);
                uint2 a1 = *(const uint2*)(pb + (m0w + gid + 8) * 416 + kb * 32 + sw);
                #pragma unroll
                for (int ni = 0; ni < 4; ni++) {
                    int d = cg * 32 + ni * 8 + gid;
                    uint2 bf = *(const uint2*)(vb + d * 416 + kb * 32 + sw);
                    MMA16816(oacc[ni], a0.x, a1.x, a0.y, a1.y, bf.x, bf.y);
                }
            }
        }

        float inv0 = 1.f / (reds[m0w + gid]     + reds[64 + m0w + gid]);
        float inv1 = 1.f / (reds[m0w + gid + 8] + reds[64 + m0w + gid + 8]);
        bool ok0 = (q0 + m0w + gid)     < T_SEQ;
        bool ok1 = (q0 + m0w + gid + 8) < T_SEQ;
        int gr0 = b * T_SEQ + q0 + m0w + gid;
        int gr1 = gr0 + 8;
        #pragma unroll
        for (int ni = 0; ni < 4; ni++) {
            int col = h * HS + cg * 32 + ni * 8 + tig * 2;
            if (ok0)
                *(half2*)(O + (size_t)gr0 * EMBD + poff(gr0, col)) =
                    __floats2half2_rn(oacc[ni][0] * inv0, oacc[ni][1] * inv0);
            if (ok1)
                *(half2*)(O + (size_t)gr1 * EMBD + poff(gr1, col)) =
                    __floats2half2_rn(oacc[ni][2] * inv1, oacc[ni][3] * inv1);
        }
    }
}

// ---------------- launch ----------------
extern "C" void kernel_launch(void* const* d_in, const int* in_sizes, int n_in,
                              void* d_out, int out_size)
{
    const float* x     = (const float*)d_in[0];
    const float* Wq    = (const float*)d_in[1];
    const float* Wk    = (const float*)d_in[2];
    const float* Wv    = (const float*)d_in[3];
    const float* Wproj = (const float*)d_in[4];
    const float* bproj = (const float*)d_in[5];
    const float* W1    = (const float*)d_in[6];
    const float* b1    = (const float*)d_in[7];
    const float* W2    = (const float*)d_in[8];
    const float* b2    = (const float*)d_in[9];
    const float* g1    = (const float*)d_in[10];
    const float* be1   = (const float*)d_in[11];
    const float* g2    = (const float*)d_in[12];
    const float* be2   = (const float*)d_in[13];

    __half *H, *QKV, *A, *F, *Wqkvt, *Wpt, *W1t, *W2t;
    float *X1;
    cudaGetSymbolAddress((void**)&H,     g_H);
    cudaGetSymbolAddress((void**)&QKV,   g_QKV);
    cudaGetSymbolAddress((void**)&A,     g_A);
    cudaGetSymbolAddress((void**)&X1,    g_X1);
    cudaGetSymbolAddress((void**)&F,     g_F);
    cudaGetSymbolAddress((void**)&Wqkvt, g_Wqkv);
    cudaGetSymbolAddress((void**)&Wpt,   g_Wp);
    cudaGetSymbolAddress((void**)&W1t,   g_W1t);
    cudaGetSymbolAddress((void**)&W2t,   g_W2t);

    cudaFuncSetAttribute(attn3,
                         cudaFuncAttributeMaxDynamicSharedMemorySize, ATTN3_SMEM);
    cudaFuncSetAttribute(gemm_h<0>,
                         cudaFuncAttributeMaxDynamicSharedMemorySize, GSMEM);
    cudaFuncSetAttribute(gemm_h<1>,
                         cudaFuncAttributeMaxDynamicSharedMemorySize, GSMEM);
    cudaFuncSetAttribute(gemm_h<2>,
                         cudaFuncAttributeMaxDynamicSharedMemorySize, GSMEM);

    const int nW = (EMBD * EMBD + 255) / 256;
    const int nF = (EMBD * FFN_D + 255) / 256;

    // 0) weight prep
    prep_qkv<<<3 * nW, 256>>>(Wq, Wk, Wv, Wqkvt);
    prep_w<<<nW, 256>>>(Wproj, Wpt, EMBD, EMBD);
    prep_w<<<nF, 256>>>(W1,    W1t, EMBD, FFN_D);
    prep_w<<<nF, 256>>>(W2,    W2t, FFN_D, EMBD);

    // 1) h = LN(x)  -> fp16 permuted
    ln_kernel<<<M_ROWS / 8, 256>>>(x, g1, be1, H);
    // 2) qkv = h @ [Wq|Wk|Wv]  -> fp16 natural
    gemm_h<0><<<dim3(LDQ / 128, M_ROWS / 128), 256, GSMEM>>>(
        H, Wqkvt, nullptr, nullptr, QKV, M_ROWS, LDQ, EMBD);
    // 3) attention -> fp16 permuted
    attn3<<<BATCH * NH, 256, ATTN3_SMEM>>>(QKV, A);
    // 4) x1 = x + att @ Wproj + bproj  -> fp32 natural
    gemm_h<2><<<dim3(EMBD / 128, M_ROWS / 128), 256, GSMEM>>>(
        A, Wpt, bproj, x, X1, M_ROWS, EMBD, EMBD);
    // 5) h2 = LN(x1) -> fp16 permuted
    ln_kernel<<<M_ROWS / 8, 256>>>(X1, g2, be2, H);
    // 6) f = relu(h2 @ W1 + b1) -> fp16 permuted
    gemm_h<1><<<dim3(FFN_D / 128, M_ROWS / 128), 256, GSMEM>>>(
        H, W1t, b1, nullptr, F, M_ROWS, FFN_D, EMBD);
    // 7) out = x1 + f @ W2 + b2 -> fp32 natural
    gemm_h<2><<<dim3(EMBD / 128, M_ROWS / 128), 256, GSMEM>>>(
        F, W2t, b2, X1, (float*)d_out, M_ROWS, EMBD, FFN_D);
}

// round 15
// speedup vs baseline: 1.0276x; 1.0276x over previous
#include <cuda_runtime.h>
#include <cuda_fp16.h>
#include <cstdint>

#define EMBD   384
#define FFN_D  1536
#define T_SEQ  200
#define NH     6
#define HS     64
#define BATCH  256
#define M_ROWS (BATCH * T_SEQ)   // 51200
#define LDQ    1152              // fused QKV row stride

// ---------------- scratch (no allocations allowed) ----------------
__device__ __half g_H [M_ROWS * EMBD];     // LN out, fp16 permuted
__device__ __half g_QKV[M_ROWS * LDQ];     // fp16 natural
__device__ __half g_A [M_ROWS * EMBD];     // attn out, fp16 permuted
__device__ float  g_X1[M_ROWS * EMBD];     // fp32 natural
__device__ __half g_F [M_ROWS * FFN_D];    // relu out, fp16 permuted
// fp16 weights: Wt[N][K], k pair-permuted
__device__ __half g_Wqkv[LDQ * EMBD];
__device__ __half g_Wp  [EMBD * EMBD];
__device__ __half g_W1t [FFN_D * EMBD];
__device__ __half g_W2t [EMBD * FFN_D];

// ---------------- permuted fp16 layout (k-pair permutation only; no bank XOR —
// conflict avoidance now comes from the 96B SMEM row stride in the GEMM) ------
__device__ __forceinline__ int poff(int m, int k) {
    int b = k & 15;
    int p = b >> 1, o = b & 1;
    int pp = ((p & 3) << 1) | (p >> 2);
    return (k & ~15) | (pp << 1) | o;
}

// ---------------- helpers ----------------
__device__ __forceinline__ uint32_t smem_u32(const void* p) {
    uint32_t a;
    asm("{ .reg .u64 t; cvta.to.shared.u64 t, %1; cvt.u32.u64 %0, t; }"
        : "=r"(a) : "l"(p));
    return a;
}
__device__ __forceinline__ void cp16(uint32_t dst, const void* src) {
    asm volatile("cp.async.cg.shared.global [%0], [%1], 16;" :: "r"(dst), "l"(src));
}
#define CP_COMMIT()  asm volatile("cp.async.commit_group;" ::: "memory")
#define CP_WAIT(n)   asm volatile("cp.async.wait_group %0;" :: "n"(n) : "memory")

#define MMA16816(acc, a0, a1, a2, a3, b0, b1)                          \
    asm volatile(                                                      \
        "mma.sync.aligned.m16n8k16.row.col.f32.f16.f16.f32 "           \
        "{%0,%1,%2,%3}, {%4,%5,%6,%7}, {%8,%9}, {%0,%1,%2,%3};"        \
        : "+f"((acc)[0]), "+f"((acc)[1]), "+f"((acc)[2]), "+f"((acc)[3]) \
        : "r"(a0), "r"(a1), "r"(a2), "r"(a3), "r"(b0), "r"(b1))

// ---------------- weight prep ----------------
__global__ void prep_w(const float* __restrict__ src, __half* __restrict__ dst,
                       int K, int N)
{
    int idx = blockIdx.x * 256 + threadIdx.x;
    if (idx >= K * N) return;
    int k = idx / N, n = idx - k * N;
    dst[(size_t)n * K + poff(n, k)] = __float2half(src[idx]);
}

__global__ void prep_qkv(const float* __restrict__ Wq,
                         const float* __restrict__ Wk,
                         const float* __restrict__ Wv,
                         __half* __restrict__ dst)
{
    int idx = blockIdx.x * 256 + threadIdx.x;
    if (idx >= 3 * EMBD * EMBD) return;
    int which = idx / (EMBD * EMBD);
    int rem = idx - which * EMBD * EMBD;
    int k = rem / EMBD, n = rem - k * EMBD;
    const float* src = (which == 0) ? Wq : (which == 1) ? Wk : Wv;
    dst[(size_t)(which * EMBD + n) * EMBD + poff(n, k)] = __float2half(src[rem]);
}

// ---------------- LayerNorm: warp per row -> fp16 permuted ----------------
__global__ void ln_kernel(const float* __restrict__ x,
                          const float* __restrict__ g,
                          const float* __restrict__ be,
                          __half* __restrict__ out)
{
    int warp = threadIdx.x >> 5, lane = threadIdx.x & 31;
    int row = blockIdx.x * 8 + warp;
    const float4* xr = (const float4*)(x + (size_t)row * EMBD);

    float4 v0 = xr[lane], v1 = xr[lane + 32], v2 = xr[lane + 64];
    float s = v0.x + v0.y + v0.z + v0.w + v1.x + v1.y + v1.z + v1.w
            + v2.x + v2.y + v2.z + v2.w;
    #pragma unroll
    for (int o = 16; o; o >>= 1) s += __shfl_xor_sync(0xffffffffu, s, o);
    float mean = s * (1.0f / EMBD);

    float sq = 0.f;
    #pragma unroll
    for (int c = 0; c < 3; c++) {
        float4 v = c == 0 ? v0 : c == 1 ? v1 : v2;
        float a = v.x - mean, b_ = v.y - mean, cc = v.z - mean, d = v.w - mean;
        sq += a * a + b_ * b_ + cc * cc + d * d;
    }
    #pragma unroll
    for (int o = 16; o; o >>= 1) sq += __shfl_xor_sync(0xffffffffu, sq, o);
    float inv = rsqrtf(sq * (1.0f / EMBD) + 1e-5f);

    __half* orow = out + (size_t)row * EMBD;
    #pragma unroll
    for (int c = 0; c < 3; c++) {
        float4 v = c == 0 ? v0 : c == 1 ? v1 : v2;
        int k0 = c * 128 + lane * 4;
        const float4 gg = *(const float4*)(g + k0);
        const float4 bb = *(const float4*)(be + k0);
        float r0 = (v.x - mean) * inv * gg.x + bb.x;
        float r1 = (v.y - mean) * inv * gg.y + bb.y;
        float r2 = (v.z - mean) * inv * gg.z + bb.z;
        float r3 = (v.w - mean) * inv * gg.w + bb.w;
        *(half2*)(orow + poff(row, k0))     = __floats2half2_rn(r0, r1);
        *(half2*)(orow + poff(row, k0 + 2)) = __floats2half2_rn(r2, r3);
    }
}

// ---------------- fp16 tensor-core GEMM, 96B-stride SMEM (conflict-free) ----
// CTA 128x128, 8 warps (4Mx2N), warp tile 32x64 = 2x8 m16n8k16, 3-stage.
// SMEM rows are 96B (64B payload + 32B pad): bank offset gid*24 mod 32 =
// {0,24,16,8} -> the 16-lane LDS.64 phase covers all 32 banks exactly once.
// EPI: 0 = fp16 natural out, 1 = bias+relu (fp16 permuted), 2 = bias+residual (fp32).
#define GST     96
#define STAGE_B (128 * GST)       // 12288 per matrix per stage
#define GSMEM   (6 * STAGE_B)     // 73728: A stages [0,3), B stages [3,6)

template <int EPI>
__global__ void __launch_bounds__(256)
gemm_h(const __half* __restrict__ A,
       const __half* __restrict__ Bt,
       const float* __restrict__ bias,
       const float* __restrict__ add,
       void* __restrict__ Cv,
       int M, int N, int K)
{
    extern __shared__ char gsm[];

    const int tid  = threadIdx.x;
    const int warp = tid >> 5, lane = tid & 31;
    const int wm   = warp >> 1, wn = warp & 1;
    const int gid  = lane >> 2, tig = lane & 3;
    const int m0   = blockIdx.y * 128, n0 = blockIdx.x * 128;

    const int lr = tid >> 1;           // row 0..127
    const int lc = (tid & 1) * 32;     // byte offset within 64B payload

    const char* Ag = (const char*)(A + (size_t)(m0 + lr) * K) + lc;
    const char* Bg = (const char*)(Bt + (size_t)(n0 + lr) * K) + lc;
    const uint32_t asm0 = smem_u32(gsm) + lr * GST + lc;
    const uint32_t bsm0 = asm0 + 3 * STAGE_B;

    float acc[2][8][4];
    #pragma unroll
    for (int i = 0; i < 2; i++)
        #pragma unroll
        for (int j = 0; j < 8; j++)
            #pragma unroll
            for (int l = 0; l < 4; l++) acc[i][j][l] = 0.f;

    const int S = K / 32;   // 12 or 48; divisible by 3

    auto load_stage = [&](int buf, int k0) {
        const char* a = Ag + (size_t)k0 * 2;
        const char* b = Bg + (size_t)k0 * 2;
        uint32_t da = asm0 + buf * STAGE_B, db = bsm0 + buf * STAGE_B;
        cp16(da, a); cp16(da + 16, a + 16);
        cp16(db, b); cp16(db + 16, b + 16);
        CP_COMMIT();
    };

    load_stage(0, 0);
    load_stage(1, 32);

    const int cx = tig << 3;           // direct chunk select (no XOR needed)
    const char* asb = (const char*)gsm;
    const char* bsb = asb + 3 * STAGE_B;

    auto step = [&](int cur, int nxt, int s) {
        CP_WAIT(1);
        __syncthreads();
        int k2 = (s + 2) * 32;
        if (k2 < K) load_stage(nxt, k2);
        else        CP_COMMIT();

        const char* a_sm = asb + cur * STAGE_B;
        const char* b_sm = bsb + cur * STAGE_B;

        #pragma unroll
        for (int blk = 0; blk < 2; blk++) {
            const int bo = blk * 32 + cx;
            uint2 af[2][2];
            #pragma unroll
            for (int mi = 0; mi < 2; mi++) {
                int base = (wm * 32 + mi * 16 + gid) * GST + bo;
                af[mi][0] = *(const uint2*)(a_sm + base);
                af[mi][1] = *(const uint2*)(a_sm + base + 8 * GST);
            }
            uint2 bf[8];
            #pragma unroll
            for (int ni = 0; ni < 8; ni++)
                bf[ni] = *(const uint2*)(b_sm + (wn * 64 + ni * 8 + gid) * GST + bo);

            #pragma unroll
            for (int mi = 0; mi < 2; mi++)
                #pragma unroll
                for (int ni = 0; ni < 8; ni++)
                    MMA16816(acc[mi][ni],
                             af[mi][0].x, af[mi][1].x, af[mi][0].y, af[mi][1].y,
                             bf[ni].x, bf[ni].y);
        }
    };

    #pragma unroll 1
    for (int s = 0; s < S; s += 3) {
        step(0, 2, s);
        step(1, 0, s + 1);
        step(2, 1, s + 2);
    }

    // ---------------- epilogue ----------------
    float bx[16];
    if (EPI != 0) {
        #pragma unroll
        for (int ni = 0; ni < 8; ni++) {
            int c = n0 + wn * 64 + ni * 8 + tig * 2;
            bx[ni * 2]     = bias[c];
            bx[ni * 2 + 1] = bias[c + 1];
        }
    }
    #pragma unroll
    for (int mi = 0; mi < 2; mi++) {
        int r = m0 + wm * 32 + mi * 16 + gid;
        #pragma unroll
        for (int ni = 0; ni < 8; ni++) {
            int c = n0 + wn * 64 + ni * 8 + tig * 2;
            float v00 = acc[mi][ni][0], v01 = acc[mi][ni][1];
            float v10 = acc[mi][ni][2], v11 = acc[mi][ni][3];
            if (EPI == 0) {
                __half* Ch = (__half*)Cv;
                *(half2*)(Ch + (size_t)r * N + c)       = __floats2half2_rn(v00, v01);
                *(half2*)(Ch + (size_t)(r + 8) * N + c) = __floats2half2_rn(v10, v11);
            } else if (EPI == 1) {
                v00 = fmaxf(v00 + bx[ni * 2], 0.f);     v01 = fmaxf(v01 + bx[ni * 2 + 1], 0.f);
                v10 = fmaxf(v10 + bx[ni * 2], 0.f);     v11 = fmaxf(v11 + bx[ni * 2 + 1], 0.f);
                __half* Ch = (__half*)Cv;
                int off = poff(r, c);
                *(half2*)(Ch + (size_t)r * N + off)       = __floats2half2_rn(v00, v01);
                *(half2*)(Ch + (size_t)(r + 8) * N + off) = __floats2half2_rn(v10, v11);
            } else {
                float* Cf = (float*)Cv;
                float2 r0v = *(const float2*)(add + (size_t)r * N + c);
                float2 r1v = *(const float2*)(add + (size_t)(r + 8) * N + c);
                v00 += bx[ni * 2] + r0v.x; v01 += bx[ni * 2 + 1] + r0v.y;
                v10 += bx[ni * 2] + r1v.x; v11 += bx[ni * 2 + 1] + r1v.y;
                *(float2*)(Cf + (size_t)r * N + c)       = make_float2(v00, v01);
                *(float2*)(Cf + (size_t)(r + 8) * N + c) = make_float2(v10, v11);
            }
        }
    }
}

// ---------------- tensor-core attention, one block per (b,h) ----------------
#define KPAD 208
#define AT_K 4096
#define AT_V 16896
#define AT_P 30208
#define AT_RED 43520
#define ATTN3_SMEM (43520 * 2 + 1024)

__global__ void __launch_bounds__(256)
attn3(const __half* __restrict__ QKV, __half* __restrict__ O)
{
    extern __shared__ __half sm2[];
    __half* Qs = sm2;                  // [64][64]
    __half* Ks = sm2 + AT_K;           // [200][64]
    __half* Vt = sm2 + AT_V;           // [64][208]
    __half* Ps = sm2 + AT_P;           // [64][208]
    float* redm = (float*)(sm2 + AT_RED);   // [2][64]
    float* reds = redm + 128;               // [2][64]

    const int bh = blockIdx.x;
    const int b = bh / NH, h = bh % NH;
    const __half* base = QKV + (size_t)b * T_SEQ * LDQ + h * HS;

    const int tid = threadIdx.x, warp = tid >> 5, lane = tid & 31;
    const int gid = lane >> 2, tig = lane & 3;
    const int rg = warp >> 1, cg = warp & 1;
    const int sw = tig << 3;           // matches XOR-free poff placement
    const half2 zz = __floats2half2_rn(0.f, 0.f);

    for (int i = tid; i < T_SEQ * 32; i += 256) {
        int j = i >> 5, dp = (i & 31) * 2;
        half2 v = *(const half2*)(base + (size_t)j * LDQ + EMBD + dp);
        *(half2*)(Ks + j * 64 + poff(j, dp)) = v;
    }
    for (int i = tid; i < (T_SEQ / 2) * HS; i += 256) {
        int jp = (i >> 6) * 2, d = i & 63;
        __half v0 = base[(size_t)jp * LDQ + 2 * EMBD + d];
        __half v1 = base[(size_t)(jp + 1) * LDQ + 2 * EMBD + d];
        *(half2*)(Vt + d * KPAD + poff(d, jp)) = __halves2half2(v0, v1);
    }
    for (int i = tid; i < HS * 4; i += 256) {
        int d = i >> 2, j = T_SEQ + (i & 3) * 2;
        *(half2*)(Vt + d * KPAD + poff(d, j)) = zz;
    }
    __syncthreads();

    const float scale = 0.05103103630798288f;   // 384^-0.5
    const int m0w = rg * 16;
    const char* qb = (const char*)Qs;
    const char* kbp = (const char*)Ks;
    char* pb = (char*)Ps;
    const char* vb = (const char*)Vt;

    for (int qt = 0; qt < 4; qt++) {
        const int q0 = qt * 64;
        const int jmax = (qt < 3) ? (q0 + 64) : T_SEQ;
        const int NT = (jmax + 7) >> 3;
        const int KB = (jmax + 15) >> 4;

        for (int i = tid; i < 64 * 32; i += 256) {
            int r = i >> 5, dp = (i & 31) * 2;
            int gq = q0 + r;
            half2 v = (gq < T_SEQ) ? *(const half2*)(base + (size_t)gq * LDQ + dp) : zz;
            *(half2*)(Qs + r * 64 + poff(r, dp)) = v;
        }
        __syncthreads();

        float acc[13][4];
        #pragma unroll
        for (int ii = 0; ii < 13; ii++)
            #pragma unroll
            for (int l = 0; l < 4; l++) acc[ii][l] = 0.f;

        #pragma unroll
        for (int kb = 0; kb < 4; kb++) {
            uint2 a0 = *(const uint2*)(qb + (m0w + gid) * 128 + kb * 32 + sw);
            uint2 a1 = *(const uint2*)(qb + (m0w + gid + 8) * 128 + kb * 32 + sw);
            #pragma unroll
            for (int ii = 0; ii < 13; ii++) {
                int jt = cg + ii * 2;
                if (jt < NT) {
                    uint2 bf = *(const uint2*)(kbp + (jt * 8 + gid) * 128 + kb * 32 + sw);
                    MMA16816(acc[ii], a0.x, a1.x, a0.y, a1.y, bf.x, bf.y);
                }
            }
        }

        const int r0 = q0 + m0w + gid, r1 = r0 + 8;
        float mx0 = -1e30f, mx1 = -1e30f;
        #pragma unroll
        for (int ii = 0; ii < 13; ii++) {
            int jt = cg + ii * 2;
            if (jt < NT) {
                int j0 = jt * 8 + tig * 2;
                acc[ii][0] = (j0     <= r0) ? acc[ii][0] * scale : -1e30f;
                acc[ii][1] = (j0 + 1 <= r0) ? acc[ii][1] * scale : -1e30f;
                acc[ii][2] = (j0     <= r1) ? acc[ii][2] * scale : -1e30f;
                acc[ii][3] = (j0 + 1 <= r1) ? acc[ii][3] * scale : -1e30f;
                mx0 = fmaxf(mx0, fmaxf(acc[ii][0], acc[ii][1]));
                mx1 = fmaxf(mx1, fmaxf(acc[ii][2], acc[ii][3]));
            }
        }
        mx0 = fmaxf(mx0, __shfl_xor_sync(0xffffffffu, mx0, 1));
        mx0 = fmaxf(mx0, __shfl_xor_sync(0xffffffffu, mx0, 2));
        mx1 = fmaxf(mx1, __shfl_xor_sync(0xffffffffu, mx1, 1));
        mx1 = fmaxf(mx1, __shfl_xor_sync(0xffffffffu, mx1, 2));
        if (tig == 0) {
            redm[cg * 64 + m0w + gid]     = mx0;
            redm[cg * 64 + m0w + gid + 8] = mx1;
        }
        __syncthreads();
        mx0 = fmaxf(redm[m0w + gid],     redm[64 + m0w + gid]);
        mx1 = fmaxf(redm[m0w + gid + 8], redm[64 + m0w + gid + 8]);

        float s0 = 0.f, s1 = 0.f;
        #pragma unroll
        for (int ii = 0; ii < 13; ii++) {
            int jt = cg + ii * 2;
            if (jt < NT) {
                int j0 = jt * 8 + tig * 2;
                float e00 = __expf(acc[ii][0] - mx0), e01 = __expf(acc[ii][1] - mx0);
                float e10 = __expf(acc[ii][2] - mx1), e11 = __expf(acc[ii][3] - mx1);
                s0 += e00 + e01; s1 += e10 + e11;
                int m_ = m0w + gid;
                *(half2*)(pb + m_ * 416 + poff(m_, j0) * 2) = __floats2half2_rn(e00, e01);
                m_ += 8;
                *(half2*)(pb + m_ * 416 + poff(m_, j0) * 2) = __floats2half2_rn(e10, e11);
            }
        }
        if (qt == 3 && cg) {
            int j0 = T_SEQ + tig * 2;
            int m_ = m0w + gid;
            *(half2*)(pb + m_ * 416 + poff(m_, j0) * 2) = zz;
            m_ += 8;
            *(half2*)(pb + m_ * 416 + poff(m_, j0) * 2) = zz;
        }
        s0 += __shfl_xor_sync(0xffffffffu, s0, 1);
        s0 += __shfl_xor_sync(0xffffffffu, s0, 2);
        s1 += __shfl_xor_sync(0xffffffffu, s1, 1);
        s1 += __shfl_xor_sync(0xffffffffu, s1, 2);
        if (tig == 0) {
            reds[cg * 64 + m0w + gid]     = s0;
            reds[cg * 64 + m0w + gid + 8] = s1;
        }
        __syncthreads();

        float oacc[4][4];
        #pragma unroll
        for (int ni = 0; ni < 4; ni++)
            #pragma unroll
            for (int l = 0; l < 4; l++) oacc[ni][l] = 0.f;

        #pragma unroll
        for (int kb = 0; kb < 13; kb++) {
            if (kb < KB) {
                uint2 a0 = *(const uint2*)(pb + (m0w + gid) * 416 + kb * 32 + sw);
                uint2 a1 = *(const uint2*)(pb + (m0w + gid + 8) * 416 + kb * 32 + sw);
                #pragma unroll
                for (int ni = 0; ni < 4; ni++) {
                    int d = cg * 32 + ni * 8 + gid;
                    uint2 bf = *(const uint2*)(vb + d * 416 + kb * 32 + sw);
                    MMA16816(oacc[ni], a0.x, a1.x, a0.y, a1.y, bf.x, bf.y);
                }
            }
        }

        float inv0 = 1.f / (reds[m0w + gid]     + reds[64 + m0w + gid]);
        float inv1 = 1.f / (reds[m0w + gid + 8] + reds[64 + m0w + gid + 8]);
        bool ok0 = (q0 + m0w + gid)     < T_SEQ;
        bool ok1 = (q0 + m0w + gid + 8) < T_SEQ;
        int gr0 = b * T_SEQ + q0 + m0w + gid;
        int gr1 = gr0 + 8;
        #pragma unroll
        for (int ni = 0; ni < 4; ni++) {
            int col = h * HS + cg * 32 + ni * 8 + tig * 2;
            if (ok0)
                *(half2*)(O + (size_t)gr0 * EMBD + poff(gr0, col)) =
                    __floats2half2_rn(oacc[ni][0] * inv0, oacc[ni][1] * inv0);
            if (ok1)
                *(half2*)(O + (size_t)gr1 * EMBD + poff(gr1, col)) =
                    __floats2half2_rn(oacc[ni][2] * inv1, oacc[ni][3] * inv1);
        }
    }
}

// ---------------- launch ----------------
extern "C" void kernel_launch(void* const* d_in, const int* in_sizes, int n_in,
                              void* d_out, int out_size)
{
    const float* x     = (const float*)d_in[0];
    const float* Wq    = (const float*)d_in[1];
    const float* Wk    = (const float*)d_in[2];
    const float* Wv    = (const float*)d_in[3];
    const float* Wproj = (const float*)d_in[4];
    const float* bproj = (const float*)d_in[5];
    const float* W1    = (const float*)d_in[6];
    const float* b1    = (const float*)d_in[7];
    const float* W2    = (const float*)d_in[8];
    const float* b2    = (const float*)d_in[9];
    const float* g1    = (const float*)d_in[10];
    const float* be1   = (const float*)d_in[11];
    const float* g2    = (const float*)d_in[12];
    const float* be2   = (const float*)d_in[13];

    __half *H, *QKV, *A, *F, *Wqkvt, *Wpt, *W1t, *W2t;
    float *X1;
    cudaGetSymbolAddress((void**)&H,     g_H);
    cudaGetSymbolAddress((void**)&QKV,   g_QKV);
    cudaGetSymbolAddress((void**)&A,     g_A);
    cudaGetSymbolAddress((void**)&X1,    g_X1);
    cudaGetSymbolAddress((void**)&F,     g_F);
    cudaGetSymbolAddress((void**)&Wqkvt, g_Wqkv);
    cudaGetSymbolAddress((void**)&Wpt,   g_Wp);
    cudaGetSymbolAddress((void**)&W1t,   g_W1t);
    cudaGetSymbolAddress((void**)&W2t,   g_W2t);

    cudaFuncSetAttribute(attn3,
                         cudaFuncAttributeMaxDynamicSharedMemorySize, ATTN3_SMEM);
    cudaFuncSetAttribute(gemm_h<0>,
                         cudaFuncAttributeMaxDynamicSharedMemorySize, GSMEM);
    cudaFuncSetAttribute(gemm_h<1>,
                         cudaFuncAttributeMaxDynamicSharedMemorySize, GSMEM);
    cudaFuncSetAttribute(gemm_h<2>,
                         cudaFuncAttributeMaxDynamicSharedMemorySize, GSMEM);

    const int nW = (EMBD * EMBD + 255) / 256;
    const int nF = (EMBD * FFN_D + 255) / 256;

    // 0) weight prep
    prep_qkv<<<3 * nW, 256>>>(Wq, Wk, Wv, Wqkvt);
    prep_w<<<nW, 256>>>(Wproj, Wpt, EMBD, EMBD);
    prep_w<<<nF, 256>>>(W1,    W1t, EMBD, FFN_D);
    prep_w<<<nF, 256>>>(W2,    W2t, FFN_D, EMBD);

    // 1) h = LN(x)  -> fp16 permuted
    ln_kernel<<<M_ROWS / 8, 256>>>(x, g1, be1, H);
    // 2) qkv = h @ [Wq|Wk|Wv]  -> fp16 natural
    gemm_h<0><<<dim3(LDQ / 128, M_ROWS / 128), 256, GSMEM>>>(
        H, Wqkvt, nullptr, nullptr, QKV, M_ROWS, LDQ, EMBD);
    // 3) attention -> fp16 permuted
    attn3<<<BATCH * NH, 256, ATTN3_SMEM>>>(QKV, A);
    // 4) x1 = x + att @ Wproj + bproj  -> fp32 natural
    gemm_h<2><<<dim3(EMBD / 128, M_ROWS / 128), 256, GSMEM>>>(
        A, Wpt, bproj, x, X1, M_ROWS, EMBD, EMBD);
    // 5) h2 = LN(x1) -> fp16 permuted
    ln_kernel<<<M_ROWS / 8, 256>>>(X1, g2, be2, H);
    // 6) f = relu(h2 @ W1 + b1) -> fp16 permuted
    gemm_h<1><<<dim3(FFN_D / 128, M_ROWS / 128), 256, GSMEM>>>(
        H, W1t, b1, nullptr, F, M_ROWS, FFN_D, EMBD);
    // 7) out = x1 + f @ W2 + b2 -> fp32 natural
    gemm_h<2><<<dim3(EMBD / 128, M_ROWS / 128), 256, GSMEM>>>(
        F, W2t, b2, X1, (float*)d_out, M_ROWS, EMBD, FFN_D);
}

// round 17
// speedup vs baseline: 1.0367x; 1.0088x over previous
#include <cuda_runtime.h>
#include <cuda_fp16.h>
#include <cstdint>

#define EMBD   384
#define FFN_D  1536
#define T_SEQ  200
#define NH     6
#define HS     64
#define BATCH  256
#define M_ROWS (BATCH * T_SEQ)   // 51200
#define LDQ    1152              // fused QKV row stride

// ---------------- scratch (no allocations allowed) ----------------
__device__ __half g_H [M_ROWS * EMBD];     // LN out, fp16 permuted
__device__ __half g_QKV[M_ROWS * LDQ];     // fp16 natural
__device__ __half g_A [M_ROWS * EMBD];     // attn out, fp16 permuted
__device__ float  g_X1[M_ROWS * EMBD];     // fp32 natural
__device__ __half g_F [M_ROWS * FFN_D];    // relu out, fp16 permuted
// fp16 weights: Wt[N][K], k pair-permuted
__device__ __half g_Wqkv[LDQ * EMBD];
__device__ __half g_Wp  [EMBD * EMBD];
__device__ __half g_W1t [FFN_D * EMBD];
__device__ __half g_W2t [EMBD * FFN_D];

// ---------------- permuted fp16 layout (k-pair permutation only) ----------------
__device__ __forceinline__ int poff(int m, int k) {
    int b = k & 15;
    int p = b >> 1, o = b & 1;
    int pp = ((p & 3) << 1) | (p >> 2);
    return (k & ~15) | (pp << 1) | o;
}

// ---------------- helpers ----------------
__device__ __forceinline__ uint32_t smem_u32(const void* p) {
    uint32_t a;
    asm("{ .reg .u64 t; cvta.to.shared.u64 t, %1; cvt.u32.u64 %0, t; }"
        : "=r"(a) : "l"(p));
    return a;
}
__device__ __forceinline__ void cp16(uint32_t dst, const void* src) {
    asm volatile("cp.async.cg.shared.global [%0], [%1], 16;" :: "r"(dst), "l"(src));
}
#define CP_COMMIT()  asm volatile("cp.async.commit_group;" ::: "memory")
#define CP_WAIT(n)   asm volatile("cp.async.wait_group %0;" :: "n"(n) : "memory")

#define MMA16816(acc, a0, a1, a2, a3, b0, b1)                          \
    asm volatile(                                                      \
        "mma.sync.aligned.m16n8k16.row.col.f32.f16.f16.f32 "           \
        "{%0,%1,%2,%3}, {%4,%5,%6,%7}, {%8,%9}, {%0,%1,%2,%3};"        \
        : "+f"((acc)[0]), "+f"((acc)[1]), "+f"((acc)[2]), "+f"((acc)[3]) \
        : "r"(a0), "r"(a1), "r"(a2), "r"(a3), "r"(b0), "r"(b1))

// ---------------- LN row helper (warp-collective) ----------------
__device__ __forceinline__ void ln_row(const float* __restrict__ x,
                                       const float* __restrict__ g,
                                       const float* __restrict__ be,
                                       __half* __restrict__ out,
                                       int row, int lane)
{
    const float4* xr = (const float4*)(x + (size_t)row * EMBD);
    float4 v0 = xr[lane], v1 = xr[lane + 32], v2 = xr[lane + 64];
    float s = v0.x + v0.y + v0.z + v0.w + v1.x + v1.y + v1.z + v1.w
            + v2.x + v2.y + v2.z + v2.w;
    #pragma unroll
    for (int o = 16; o; o >>= 1) s += __shfl_xor_sync(0xffffffffu, s, o);
    float mean = s * (1.0f / EMBD);

    float sq = 0.f;
    #pragma unroll
    for (int c = 0; c < 3; c++) {
        float4 v = c == 0 ? v0 : c == 1 ? v1 : v2;
        float a = v.x - mean, b_ = v.y - mean, cc = v.z - mean, d = v.w - mean;
        sq += a * a + b_ * b_ + cc * cc + d * d;
    }
    #pragma unroll
    for (int o = 16; o; o >>= 1) sq += __shfl_xor_sync(0xffffffffu, sq, o);
    float inv = rsqrtf(sq * (1.0f / EMBD) + 1e-5f);

    __half* orow = out + (size_t)row * EMBD;
    #pragma unroll
    for (int c = 0; c < 3; c++) {
        float4 v = c == 0 ? v0 : c == 1 ? v1 : v2;
        int k0 = c * 128 + lane * 4;
        const float4 gg = *(const float4*)(g + k0);
        const float4 bb = *(const float4*)(be + k0);
        float r0 = (v.x - mean) * inv * gg.x + bb.x;
        float r1 = (v.y - mean) * inv * gg.y + bb.y;
        float r2 = (v.z - mean) * inv * gg.z + bb.z;
        float r3 = (v.w - mean) * inv * gg.w + bb.w;
        *(half2*)(orow + poff(row, k0))     = __floats2half2_rn(r0, r1);
        *(half2*)(orow + poff(row, k0 + 2)) = __floats2half2_rn(r2, r3);
    }
}

// ---------------- prep helper ----------------
__device__ __forceinline__ void prep_elem(const float* __restrict__ src,
                                          __half* __restrict__ dst,
                                          int idx, int K, int N)
{
    int k = idx / N, n = idx - k * N;
    dst[(size_t)n * K + poff(n, k)] = __float2half(src[idx]);
}

// ---------------- fused prologue: all weight prep + LN1 in one launch ------
// blocks [0,1728): Wq|Wk|Wv   [1728,2304): Wproj
// [2304,4608): W1   [4608,6912): W2   [6912,13312): LN1 (8 rows each)
#define PRO_BLOCKS 13312

__global__ void prologue(const float* __restrict__ Wq,
                         const float* __restrict__ Wk,
                         const float* __restrict__ Wv,
                         const float* __restrict__ Wproj,
                         const float* __restrict__ W1,
                         const float* __restrict__ W2,
                         const float* __restrict__ x,
                         const float* __restrict__ g1,
                         const float* __restrict__ be1,
                         __half* __restrict__ Wqkvt,
                         __half* __restrict__ Wpt,
                         __half* __restrict__ W1t,
                         __half* __restrict__ W2t,
                         __half* __restrict__ H)
{
    int blk = blockIdx.x, tid = threadIdx.x;
    if (blk < 1728) {
        int idx = blk * 256 + tid;                 // 3*EMBD*EMBD = 442368
        int which = idx / (EMBD * EMBD);
        int rem = idx - which * (EMBD * EMBD);
        int k = rem / EMBD, n = rem - k * EMBD;
        const float* src = (which == 0) ? Wq : (which == 1) ? Wk : Wv;
        Wqkvt[(size_t)(which * EMBD + n) * EMBD + poff(n, k)] = __float2half(src[rem]);
    } else if (blk < 2304) {
        prep_elem(Wproj, Wpt, (blk - 1728) * 256 + tid, EMBD, EMBD);
    } else if (blk < 4608) {
        prep_elem(W1, W1t, (blk - 2304) * 256 + tid, EMBD, FFN_D);
    } else if (blk < 6912) {
        prep_elem(W2, W2t, (blk - 4608) * 256 + tid, FFN_D, EMBD);
    } else {
        int warp = tid >> 5, lane = tid & 31;
        int row = (blk - 6912) * 8 + warp;
        ln_row(x, g1, be1, H, row, lane);
    }
}

// ---------------- LayerNorm (standalone, for LN2) ----------------
__global__ void ln_kernel(const float* __restrict__ x,
                          const float* __restrict__ g,
                          const float* __restrict__ be,
                          __half* __restrict__ out)
{
    int warp = threadIdx.x >> 5, lane = threadIdx.x & 31;
    ln_row(x, g, be, out, blockIdx.x * 8 + warp, lane);
}

// ---------------- fp16 tensor-core GEMM, 96B-stride SMEM, 3-stage ----------
// Pipeline order (R15-proven): CP_WAIT(1) -> __syncthreads -> issue(s+2) ->
// compute(s). The barrier AFTER the wait is what publishes other threads'
// cp.async completions (wait_group is per-thread).
#define GST     96
#define STAGE_B (128 * GST)       // 12288 per matrix per stage
#define GSMEM   (6 * STAGE_B)     // 73728

template <int EPI>
__global__ void __launch_bounds__(256)
gemm_h(const __half* __restrict__ A,
       const __half* __restrict__ Bt,
       const float* __restrict__ bias,
       const float* __restrict__ add,
       void* __restrict__ Cv,
       int M, int N, int K)
{
    extern __shared__ char gsm[];

    const int tid  = threadIdx.x;
    const int warp = tid >> 5, lane = tid & 31;
    const int wm   = warp >> 1, wn = warp & 1;
    const int gid  = lane >> 2, tig = lane & 3;
    const int m0   = blockIdx.y * 128, n0 = blockIdx.x * 128;

    const int lr = tid >> 1;
    const int lc = (tid & 1) * 32;

    const char* Ag = (const char*)(A + (size_t)(m0 + lr) * K) + lc;
    const char* Bg = (const char*)(Bt + (size_t)(n0 + lr) * K) + lc;
    const uint32_t asm0 = smem_u32(gsm) + lr * GST + lc;
    const uint32_t bsm0 = asm0 + 3 * STAGE_B;

    float acc[2][8][4];
    #pragma unroll
    for (int i = 0; i < 2; i++)
        #pragma unroll
        for (int j = 0; j < 8; j++)
            #pragma unroll
            for (int l = 0; l < 4; l++) acc[i][j][l] = 0.f;

    const int S = K / 32;   // 12 or 48; divisible by 3

    auto load_stage = [&](int buf, int k0) {
        const char* a = Ag + (size_t)k0 * 2;
        const char* b = Bg + (size_t)k0 * 2;
        uint32_t da = asm0 + buf * STAGE_B, db = bsm0 + buf * STAGE_B;
        cp16(da, a); cp16(da + 16, a + 16);
        cp16(db, b); cp16(db + 16, b + 16);
        CP_COMMIT();
    };

    load_stage(0, 0);
    load_stage(1, 32);

    const int cx = tig << 3;
    const char* asb = (const char*)gsm;
    const char* bsb = asb + 3 * STAGE_B;

    auto step = [&](int cur, int nxt, int s) {
        CP_WAIT(1);
        __syncthreads();
        int k2 = (s + 2) * 32;
        if (k2 < K) load_stage(nxt, k2);
        else        CP_COMMIT();

        const char* a_sm = asb + cur * STAGE_B;
        const char* b_sm = bsb + cur * STAGE_B;

        #pragma unroll
        for (int blk = 0; blk < 2; blk++) {
            const int bo = blk * 32 + cx;
            uint2 af[2][2];
            #pragma unroll
            for (int mi = 0; mi < 2; mi++) {
                int base = (wm * 32 + mi * 16 + gid) * GST + bo;
                af[mi][0] = *(const uint2*)(a_sm + base);
                af[mi][1] = *(const uint2*)(a_sm + base + 8 * GST);
            }
            uint2 bf[8];
            #pragma unroll
            for (int ni = 0; ni < 8; ni++)
                bf[ni] = *(const uint2*)(b_sm + (wn * 64 + ni * 8 + gid) * GST + bo);

            #pragma unroll
            for (int mi = 0; mi < 2; mi++)
                #pragma unroll
                for (int ni = 0; ni < 8; ni++)
                    MMA16816(acc[mi][ni],
                             af[mi][0].x, af[mi][1].x, af[mi][0].y, af[mi][1].y,
                             bf[ni].x, bf[ni].y);
        }
    };

    #pragma unroll 1
    for (int s = 0; s < S; s += 3) {
        step(0, 2, s);
        step(1, 0, s + 1);
        step(2, 1, s + 2);
    }

    // ---------------- epilogue ----------------
    float bx[16];
    if (EPI != 0) {
        #pragma unroll
        for (int ni = 0; ni < 8; ni++) {
            int c = n0 + wn * 64 + ni * 8 + tig * 2;
            bx[ni * 2]     = bias[c];
            bx[ni * 2 + 1] = bias[c + 1];
        }
    }
    #pragma unroll
    for (int mi = 0; mi < 2; mi++) {
        int r = m0 + wm * 32 + mi * 16 + gid;
        #pragma unroll
        for (int ni = 0; ni < 8; ni++) {
            int c = n0 + wn * 64 + ni * 8 + tig * 2;
            float v00 = acc[mi][ni][0], v01 = acc[mi][ni][1];
            float v10 = acc[mi][ni][2], v11 = acc[mi][ni][3];
            if (EPI == 0) {
                __half* Ch = (__half*)Cv;
                *(half2*)(Ch + (size_t)r * N + c)       = __floats2half2_rn(v00, v01);
                *(half2*)(Ch + (size_t)(r + 8) * N + c) = __floats2half2_rn(v10, v11);
            } else if (EPI == 1) {
                v00 = fmaxf(v00 + bx[ni * 2], 0.f);     v01 = fmaxf(v01 + bx[ni * 2 + 1], 0.f);
                v10 = fmaxf(v10 + bx[ni * 2], 0.f);     v11 = fmaxf(v11 + bx[ni * 2 + 1], 0.f);
                __half* Ch = (__half*)Cv;
                int off = poff(r, c);
                *(half2*)(Ch + (size_t)r * N + off)       = __floats2half2_rn(v00, v01);
                *(half2*)(Ch + (size_t)(r + 8) * N + off) = __floats2half2_rn(v10, v11);
            } else {
                float* Cf = (float*)Cv;
                float2 r0v = *(const float2*)(add + (size_t)r * N + c);
                float2 r1v = *(const float2*)(add + (size_t)(r + 8) * N + c);
                v00 += bx[ni * 2] + r0v.x; v01 += bx[ni * 2 + 1] + r0v.y;
                v10 += bx[ni * 2] + r1v.x; v11 += bx[ni * 2 + 1] + r1v.y;
                *(float2*)(Cf + (size_t)r * N + c)       = make_float2(v00, v01);
                *(float2*)(Cf + (size_t)(r + 8) * N + c) = make_float2(v10, v11);
            }
        }
    }
}

// ---------------- tensor-core attention, one block per (b,h) ----------------
#define KPAD 208
#define AT_K 4096
#define AT_V 16896
#define AT_P 30208
#define AT_RED 43520
#define ATTN3_SMEM (43520 * 2 + 1024)

__global__ void __launch_bounds__(256)
attn3(const __half* __restrict__ QKV, __half* __restrict__ O)
{
    extern __shared__ __half sm2[];
    __half* Qs = sm2;                  // [64][64]
    __half* Ks = sm2 + AT_K;           // [200][64]
    __half* Vt = sm2 + AT_V;           // [64][208]
    __half* Ps = sm2 + AT_P;           // [64][208]
    float* redm = (float*)(sm2 + AT_RED);   // [2][64]
    float* reds = redm + 128;               // [2][64]

    const int bh = blockIdx.x;
    const int b = bh / NH, h = bh % NH;
    const __half* base = QKV + (size_t)b * T_SEQ * LDQ + h * HS;

    const int tid = threadIdx.x, warp = tid >> 5, lane = tid & 31;
    const int gid = lane >> 2, tig = lane & 3;
    const int rg = warp >> 1, cg = warp & 1;
    const int sw = tig << 3;
    const half2 zz = __floats2half2_rn(0.f, 0.f);

    for (int i = tid; i < T_SEQ * 32; i += 256) {
        int j = i >> 5, dp = (i & 31) * 2;
        half2 v = *(const half2*)(base + (size_t)j * LDQ + EMBD + dp);
        *(half2*)(Ks + j * 64 + poff(j, dp)) = v;
    }
    for (int i = tid; i < (T_SEQ / 2) * HS; i += 256) {
        int jp = (i >> 6) * 2, d = i & 63;
        __half v0 = base[(size_t)jp * LDQ + 2 * EMBD + d];
        __half v1 = base[(size_t)(jp + 1) * LDQ + 2 * EMBD + d];
        *(half2*)(Vt + d * KPAD + poff(d, jp)) = __halves2half2(v0, v1);
    }
    for (int i = tid; i < HS * 4; i += 256) {
        int d = i >> 2, j = T_SEQ + (i & 3) * 2;
        *(half2*)(Vt + d * KPAD + poff(d, j)) = zz;
    }
    __syncthreads();

    // scale * log2(e): softmax done in base-2 (exp2f = bare MUFU.EX2)
    const float scl2e = 0.07362241136265098f;
    const int m0w = rg * 16;
    const char* qb = (const char*)Qs;
    const char* kbp = (const char*)Ks;
    char* pb = (char*)Ps;
    const char* vb = (const char*)Vt;

    for (int qt = 0; qt < 4; qt++) {
        const int q0 = qt * 64;
        const int jmax = (qt < 3) ? (q0 + 64) : T_SEQ;
        const int NT = (jmax + 7) >> 3;
        const int KB = (jmax + 15) >> 4;

        for (int i = tid; i < 64 * 32; i += 256) {
            int r = i >> 5, dp = (i & 31) * 2;
            int gq = q0 + r;
            half2 v = (gq < T_SEQ) ? *(const half2*)(base + (size_t)gq * LDQ + dp) : zz;
            *(half2*)(Qs + r * 64 + poff(r, dp)) = v;
        }
        __syncthreads();

        float acc[13][4];
        #pragma unroll
        for (int ii = 0; ii < 13; ii++)
            #pragma unroll
            for (int l = 0; l < 4; l++) acc[ii][l] = 0.f;

        #pragma unroll
        for (int kb = 0; kb < 4; kb++) {
            uint2 a0 = *(const uint2*)(qb + (m0w + gid) * 128 + kb * 32 + sw);
            uint2 a1 = *(const uint2*)(qb + (m0w + gid + 8) * 128 + kb * 32 + sw);
            #pragma unroll
            for (int ii = 0; ii < 13; ii++) {
                int jt = cg + ii * 2;
                if (jt < NT) {
                    uint2 bf = *(const uint2*)(kbp + (jt * 8 + gid) * 128 + kb * 32 + sw);
                    MMA16816(acc[ii], a0.x, a1.x, a0.y, a1.y, bf.x, bf.y);
                }
            }
        }

        const int r0 = q0 + m0w + gid, r1 = r0 + 8;
        float mx0 = -1e30f, mx1 = -1e30f;
        #pragma unroll
        for (int ii = 0; ii < 13; ii++) {
            int jt = cg + ii * 2;
            if (jt < NT) {
                int j0 = jt * 8 + tig * 2;
                acc[ii][0] = (j0     <= r0) ? acc[ii][0] * scl2e : -1e30f;
                acc[ii][1] = (j0 + 1 <= r0) ? acc[ii][1] * scl2e : -1e30f;
                acc[ii][2] = (j0     <= r1) ? acc[ii][2] * scl2e : -1e30f;
                acc[ii][3] = (j0 + 1 <= r1) ? acc[ii][3] * scl2e : -1e30f;
                mx0 = fmaxf(mx0, fmaxf(acc[ii][0], acc[ii][1]));
                mx1 = fmaxf(mx1, fmaxf(acc[ii][2], acc[ii][3]));
            }
        }
        mx0 = fmaxf(mx0, __shfl_xor_sync(0xffffffffu, mx0, 1));
        mx0 = fmaxf(mx0, __shfl_xor_sync(0xffffffffu, mx0, 2));
        mx1 = fmaxf(mx1, __shfl_xor_sync(0xffffffffu, mx1, 1));
        mx1 = fmaxf(mx1, __shfl_xor_sync(0xffffffffu, mx1, 2));
        if (tig == 0) {
            redm[cg * 64 + m0w + gid]     = mx0;
            redm[cg * 64 + m0w + gid + 8] = mx1;
        }
        __syncthreads();
        mx0 = fmaxf(redm[m0w + gid],     redm[64 + m0w + gid]);
        mx1 = fmaxf(redm[m0w + gid + 8], redm[64 + m0w + gid + 8]);

        float s0 = 0.f, s1 = 0.f;
        #pragma unroll
        for (int ii = 0; ii < 13; ii++) {
            int jt = cg + ii * 2;
            if (jt < NT) {
                int j0 = jt * 8 + tig * 2;
                float e00 = exp2f(acc[ii][0] - mx0), e01 = exp2f(acc[ii][1] - mx0);
                float e10 = exp2f(acc[ii][2] - mx1), e11 = exp2f(acc[ii][3] - mx1);
                s0 += e00 + e01; s1 += e10 + e11;
                int m_ = m0w + gid;
                *(half2*)(pb + m_ * 416 + poff(m_, j0) * 2) = __floats2half2_rn(e00, e01);
                m_ += 8;
                *(half2*)(pb + m_ * 416 + poff(m_, j0) * 2) = __floats2half2_rn(e10, e11);
            }
        }
        if (qt == 3 && cg) {
            int j0 = T_SEQ + tig * 2;
            int m_ = m0w + gid;
            *(half2*)(pb + m_ * 416 + poff(m_, j0) * 2) = zz;
            m_ += 8;
            *(half2*)(pb + m_ * 416 + poff(m_, j0) * 2) = zz;
        }
        s0 += __shfl_xor_sync(0xffffffffu, s0, 1);
        s0 += __shfl_xor_sync(0xffffffffu, s0, 2);
        s1 += __shfl_xor_sync(0xffffffffu, s1, 1);
        s1 += __shfl_xor_sync(0xffffffffu, s1, 2);
        if (tig == 0) {
            reds[cg * 64 + m0w + gid]     = s0;
            reds[cg * 64 + m0w + gid + 8] = s1;
        }
        __syncthreads();

        float oacc[4][4];
        #pragma unroll
        for (int ni = 0; ni < 4; ni++)
            #pragma unroll
            for (int l = 0; l < 4; l++) oacc[ni][l] = 0.f;

        #pragma unroll
        for (int kb = 0; kb < 13; kb++) {
            if (kb < KB) {
                uint2 a0 = *(const uint2*)(pb + (m0w + gid) * 416 + kb * 32 + sw);
                uint2 a1 = *(const uint2*)(pb + (m0w + gid + 8) * 416 + kb * 32 + sw);
                #pragma unroll
                for (int ni = 0; ni < 4; ni++) {
                    int d = cg * 32 + ni * 8 + gid;
                    uint2 bf = *(const uint2*)(vb + d * 416 + kb * 32 + sw);
                    MMA16816(oacc[ni], a0.x, a1.x, a0.y, a1.y, bf.x, bf.y);
                }
            }
        }

        float inv0 = 1.f / (reds[m0w + gid]     + reds[64 + m0w + gid]);
        float inv1 = 1.f / (reds[m0w + gid + 8] + reds[64 + m0w + gid + 8]);
        bool ok0 = (q0 + m0w + gid)     < T_SEQ;
        bool ok1 = (q0 + m0w + gid + 8) < T_SEQ;
        int gr0 = b * T_SEQ + q0 + m0w + gid;
        int gr1 = gr0 + 8;
        #pragma unroll
        for (int ni = 0; ni < 4; ni++) {
            int col = h * HS + cg * 32 + ni * 8 + tig * 2;
            if (ok0)
                *(half2*)(O + (size_t)gr0 * EMBD + poff(gr0, col)) =
                    __floats2half2_rn(oacc[ni][0] * inv0, oacc[ni][1] * inv0);
            if (ok1)
                *(half2*)(O + (size_t)gr1 * EMBD + poff(gr1, col)) =
                    __floats2half2_rn(oacc[ni][2] * inv1, oacc[ni][3] * inv1);
        }
    }
}

// ---------------- launch ----------------
extern "C" void kernel_launch(void* const* d_in, const int* in_sizes, int n_in,
                              void* d_out, int out_size)
{
    const float* x     = (const float*)d_in[0];
    const float* Wq    = (const float*)d_in[1];
    const float* Wk    = (const float*)d_in[2];
    const float* Wv    = (const float*)d_in[3];
    const float* Wproj = (const float*)d_in[4];
    const float* bproj = (const float*)d_in[5];
    const float* W1    = (const float*)d_in[6];
    const float* b1    = (const float*)d_in[7];
    const float* W2    = (const float*)d_in[8];
    const float* b2    = (const float*)d_in[9];
    const float* g1    = (const float*)d_in[10];
    const float* be1   = (const float*)d_in[11];
    const float* g2    = (const float*)d_in[12];
    const float* be2   = (const float*)d_in[13];

    __half *H, *QKV, *A, *F, *Wqkvt, *Wpt, *W1t, *W2t;
    float *X1;
    cudaGetSymbolAddress((void**)&H,     g_H);
    cudaGetSymbolAddress((void**)&QKV,   g_QKV);
    cudaGetSymbolAddress((void**)&A,     g_A);
    cudaGetSymbolAddress((void**)&X1,    g_X1);
    cudaGetSymbolAddress((void**)&F,     g_F);
    cudaGetSymbolAddress((void**)&Wqkvt, g_Wqkv);
    cudaGetSymbolAddress((void**)&Wpt,   g_Wp);
    cudaGetSymbolAddress((void**)&W1t,   g_W1t);
    cudaGetSymbolAddress((void**)&W2t,   g_W2t);

    cudaFuncSetAttribute(attn3,
                         cudaFuncAttributeMaxDynamicSharedMemorySize, ATTN3_SMEM);
    cudaFuncSetAttribute(gemm_h<0>,
                         cudaFuncAttributeMaxDynamicSharedMemorySize, GSMEM);
    cudaFuncSetAttribute(gemm_h<1>,
                         cudaFuncAttributeMaxDynamicSharedMemorySize, GSMEM);
    cudaFuncSetAttribute(gemm_h<2>,
                         cudaFuncAttributeMaxDynamicSharedMemorySize, GSMEM);

    // 0+1) all weight prep + LN1 fused into one launch
    prologue<<<PRO_BLOCKS, 256>>>(Wq, Wk, Wv, Wproj, W1, W2,
                                  x, g1, be1,
                                  Wqkvt, Wpt, W1t, W2t, H);
    // 2) qkv = h @ [Wq|Wk|Wv]  -> fp16 natural
    gemm_h<0><<<dim3(LDQ / 128, M_ROWS / 128), 256, GSMEM>>>(
        H, Wqkvt, nullptr, nullptr, QKV, M_ROWS, LDQ, EMBD);
    // 3) attention -> fp16 permuted
    attn3<<<BATCH * NH, 256, ATTN3_SMEM>>>(QKV, A);
    // 4) x1 = x + att @ Wproj + bproj  -> fp32 natural
    gemm_h<2><<<dim3(EMBD / 128, M_ROWS / 128), 256, GSMEM>>>(
        A, Wpt, bproj, x, X1, M_ROWS, EMBD, EMBD);
    // 5) h2 = LN(x1) -> fp16 permuted
    ln_kernel<<<M_ROWS / 8, 256>>>(X1, g2, be2, H);
    // 6) f = relu(h2 @ W1 + b1) -> fp16 permuted
    gemm_h<1><<<dim3(FFN_D / 128, M_ROWS / 128), 256, GSMEM>>>(
        H, W1t, b1, nullptr, F, M_ROWS, FFN_D, EMBD);
    // 7) out = x1 + f @ W2 + b2 -> fp32 natural
    gemm_h<2><<<dim3(EMBD / 128, M_ROWS / 128), 256, GSMEM>>>(
        F, W2t, b2, X1, (float*)d_out, M_ROWS, EMBD, FFN_D);
}